// round 1
// baseline (speedup 1.0000x reference)
#include <cuda_runtime.h>
#include <cuda_bf16.h>
#include <cstdint>

// DIFFormerConv: linear attention over 65536 nodes, 4 heads, D=256, IN=512.
// Pipeline:
//   1) convert x, Wq/Wk/Wv to bf16
//   2) colsum(x) -> vsum = colsum@Wv + N*bv   (exact fp32; dominates output)
//   3) q,k,v projections (bf16 mma.sync GEMM, fp32 accum, +bias, store bf16)
//   4) in-place L2 normalize q,k per (node,head)
//   5) ksum = column-sums of kn (deterministic 2-stage)
//   6) invden[n,h] = 1/(qn . ksum + N)
//   7) kv[h] = kn^T @ v (split-K into partials, deterministic reduce -> bf16)
//   8) out = 0.25 * sum_h (qn@kv[h] + vsum[h]) * invden[n,h]

#define NN   65536
#define INC  512
#define HD   1024
#define DIM  256

// ---------------- scratch (device globals; no allocation allowed) ------------
__device__ __nv_bfloat16 g_xb[NN * INC];            // 64 MB
__device__ __nv_bfloat16 g_wb[3][INC * HD];         // 3 MB
__device__ __nv_bfloat16 g_q[NN * HD];              // 128 MB
__device__ __nv_bfloat16 g_k[NN * HD];              // 128 MB
__device__ __nv_bfloat16 g_v[NN * HD];              // 128 MB
__device__ float g_colsum_p[64 * INC];
__device__ float g_colsum[INC];
__device__ float g_vsum[HD];
__device__ float g_ksum_p[64 * HD];
__device__ float g_ksum[HD];
__device__ float g_kv_part[16 * 4 * DIM * DIM];     // 16 MB split-K partials
__device__ __nv_bfloat16 g_kvb[4 * DIM * DIM];
__device__ float g_invden[NN * 4];

// ---------------- mma helpers ------------------------------------------------
__device__ __forceinline__ uint32_t smem_u32(const void* p) {
    return (uint32_t)__cvta_generic_to_shared(p);
}
__device__ __forceinline__ void ldsm4(uint32_t* r, uint32_t a) {
    asm volatile("ldmatrix.sync.aligned.m8n8.x4.shared.b16 {%0,%1,%2,%3}, [%4];"
        : "=r"(r[0]), "=r"(r[1]), "=r"(r[2]), "=r"(r[3]) : "r"(a));
}
__device__ __forceinline__ void ldsm4t(uint32_t* r, uint32_t a) {
    asm volatile("ldmatrix.sync.aligned.m8n8.x4.trans.shared.b16 {%0,%1,%2,%3}, [%4];"
        : "=r"(r[0]), "=r"(r[1]), "=r"(r[2]), "=r"(r[3]) : "r"(a));
}
__device__ __forceinline__ void mma16816(float* d, const uint32_t* a, const uint32_t* b) {
    asm volatile("mma.sync.aligned.m16n8k16.row.col.f32.bf16.bf16.f32 "
        "{%0,%1,%2,%3}, {%4,%5,%6,%7}, {%8,%9}, {%0,%1,%2,%3};"
        : "+f"(d[0]), "+f"(d[1]), "+f"(d[2]), "+f"(d[3])
        : "r"(a[0]), "r"(a[1]), "r"(a[2]), "r"(a[3]), "r"(b[0]), "r"(b[1]));
}

// ---------------- small kernels ---------------------------------------------
__global__ void cvt_x_kernel(const float* __restrict__ src) {
    int i = blockIdx.x * blockDim.x + threadIdx.x;
    int stride = gridDim.x * blockDim.x;
    const float4* s4 = (const float4*)src;
    __nv_bfloat162* d2 = (__nv_bfloat162*)g_xb;
    const int n4 = NN * INC / 4;
    for (int j = i; j < n4; j += stride) {
        float4 f = s4[j];
        d2[2 * j]     = __floats2bfloat162_rn(f.x, f.y);
        d2[2 * j + 1] = __floats2bfloat162_rn(f.z, f.w);
    }
}

__global__ void cvt_w_kernel(const float* __restrict__ src, int which) {
    int i = blockIdx.x * blockDim.x + threadIdx.x;
    int stride = gridDim.x * blockDim.x;
    const float4* s4 = (const float4*)src;
    __nv_bfloat162* d2 = (__nv_bfloat162*)g_wb[which];
    const int n4 = INC * HD / 4;
    for (int j = i; j < n4; j += stride) {
        float4 f = s4[j];
        d2[2 * j]     = __floats2bfloat162_rn(f.x, f.y);
        d2[2 * j + 1] = __floats2bfloat162_rn(f.z, f.w);
    }
}

// colsum of x: partials per (row-slice) for determinism
__global__ void colsum_p_kernel(const float* __restrict__ x) {
    int c = blockIdx.x * 256 + threadIdx.x;     // grid.x = 2
    int p = blockIdx.y;                          // grid.y = 64
    size_t r0 = (size_t)p * 1024;
    float s = 0.f;
    for (int r = 0; r < 1024; r++) s += x[(r0 + r) * INC + c];
    g_colsum_p[p * INC + c] = s;
}
__global__ void colsum_red_kernel() {
    int c = blockIdx.x * 256 + threadIdx.x;     // grid.x = 2
    float s = 0.f;
    for (int p = 0; p < 64; p++) s += g_colsum_p[p * INC + c];
    g_colsum[c] = s;
}

__global__ void vsum_kernel(const float* __restrict__ Wv, const float* __restrict__ bv) {
    int m = threadIdx.x;                         // 1024 threads
    float s = 0.f;
    for (int kk = 0; kk < INC; kk++) s += g_colsum[kk] * Wv[kk * HD + m];
    g_vsum[m] = s + 65536.f * bv[m];
}

// ---------------- projection GEMM: C[N,1024] = xb @ W + b, bf16 out ---------
__global__ __launch_bounds__(256) void proj_kernel(int which, const float* __restrict__ bias) {
    __shared__ __nv_bfloat16 As[128][40];   // [n-rows][k], +8 pad
    __shared__ __nv_bfloat16 Bs[32][136];   // [k][m-cols], +8 pad
    const __nv_bfloat16* __restrict__ B = g_wb[which];
    __nv_bfloat16* __restrict__ C = (which == 0) ? g_q : (which == 1) ? g_k : g_v;

    int tid = threadIdx.x, lane = tid & 31, warp = tid >> 5;
    int wm = (warp & 3) * 32, wn = (warp >> 2) * 64;
    int n0 = blockIdx.x * 128;                  // col tile
    size_t r0 = (size_t)blockIdx.y * 128;       // row tile
    int quad = lane >> 3, r8 = lane & 7;

    float acc[2][8][4];
    #pragma unroll
    for (int a = 0; a < 2; a++)
        #pragma unroll
        for (int b = 0; b < 8; b++)
            #pragma unroll
            for (int c = 0; c < 4; c++) acc[a][b][c] = 0.f;

    for (int k0 = 0; k0 < INC; k0 += 32) {
        int rowa = tid >> 2, sega = tid & 3;
        uint4 av0 = *(const uint4*)&g_xb[(r0 + rowa) * INC + k0 + sega * 8];
        uint4 av1 = *(const uint4*)&g_xb[(r0 + rowa + 64) * INC + k0 + sega * 8];
        int rowb = tid >> 4, segb = tid & 15;
        uint4 bv0 = *(const uint4*)&B[(size_t)(k0 + rowb) * HD + n0 + segb * 8];
        uint4 bv1 = *(const uint4*)&B[(size_t)(k0 + rowb + 16) * HD + n0 + segb * 8];
        __syncthreads();
        *(uint4*)&As[rowa][sega * 8] = av0;
        *(uint4*)&As[rowa + 64][sega * 8] = av1;
        *(uint4*)&Bs[rowb][segb * 8] = bv0;
        *(uint4*)&Bs[rowb + 16][segb * 8] = bv1;
        __syncthreads();
        #pragma unroll
        for (int ks = 0; ks < 32; ks += 16) {
            uint32_t af[2][4], bf[4][4];
            #pragma unroll
            for (int mi = 0; mi < 2; mi++)
                ldsm4(af[mi], smem_u32(&As[wm + mi * 16 + (quad & 1) * 8 + r8][ks + (quad >> 1) * 8]));
            #pragma unroll
            for (int nj = 0; nj < 4; nj++)
                ldsm4t(bf[nj], smem_u32(&Bs[ks + (quad & 1) * 8 + r8][wn + nj * 16 + (quad >> 1) * 8]));
            #pragma unroll
            for (int mi = 0; mi < 2; mi++)
                #pragma unroll
                for (int nj = 0; nj < 4; nj++) {
                    mma16816(acc[mi][2 * nj],     af[mi], &bf[nj][0]);
                    mma16816(acc[mi][2 * nj + 1], af[mi], &bf[nj][2]);
                }
        }
    }
    int group = lane >> 2, t4 = lane & 3;
    #pragma unroll
    for (int mi = 0; mi < 2; mi++) {
        size_t ra = r0 + wm + mi * 16 + group;
        #pragma unroll
        for (int ni = 0; ni < 8; ni++) {
            int c = n0 + wn + ni * 8 + t4 * 2;
            float b0 = bias[c], b1 = bias[c + 1];
            *(__nv_bfloat162*)&C[ra * HD + c] =
                __floats2bfloat162_rn(acc[mi][ni][0] + b0, acc[mi][ni][1] + b1);
            *(__nv_bfloat162*)&C[(ra + 8) * HD + c] =
                __floats2bfloat162_rn(acc[mi][ni][2] + b0, acc[mi][ni][3] + b1);
        }
    }
}

// ---------------- in-place per-(n,h) L2 normalize ----------------------------
__global__ void norm_kernel(int which) {
    __nv_bfloat16* buf = which ? g_k : g_q;
    int wg = blockIdx.x * 8 + (threadIdx.x >> 5);   // wg = n*4+h
    int lane = threadIdx.x & 31;
    size_t base = (size_t)wg * 256 + lane * 8;
    uint4 raw = *(const uint4*)&buf[base];
    __nv_bfloat162* p = (__nv_bfloat162*)&raw;
    float s = 0.f;
    float2 f[4];
    #pragma unroll
    for (int i = 0; i < 4; i++) {
        f[i] = __bfloat1622float2(p[i]);
        s += f[i].x * f[i].x + f[i].y * f[i].y;
    }
    #pragma unroll
    for (int o = 16; o > 0; o >>= 1) s += __shfl_xor_sync(0xffffffffu, s, o);
    float inv = rsqrtf(s);
    #pragma unroll
    for (int i = 0; i < 4; i++)
        p[i] = __floats2bfloat162_rn(f[i].x * inv, f[i].y * inv);
    *(uint4*)&buf[base] = raw;
}

// ---------------- ksum (column sums of kn), deterministic 2-stage ------------
__global__ void ksum_p_kernel() {
    int c = blockIdx.x * 256 + threadIdx.x;   // grid.x = 4
    int p = blockIdx.y;                        // grid.y = 64
    size_t r0 = (size_t)p * 1024;
    float s = 0.f;
    for (int r = 0; r < 1024; r++) s += __bfloat162float(g_k[(r0 + r) * HD + c]);
    g_ksum_p[p * HD + c] = s;
}
__global__ void ksum_red_kernel() {
    int c = blockIdx.x * 256 + threadIdx.x;   // grid.x = 4
    float s = 0.f;
    for (int p = 0; p < 64; p++) s += g_ksum_p[p * HD + c];
    g_ksum[c] = s;
}

// ---------------- invden[n,h] = 1/(qn . ksum[h] + N) -------------------------
__global__ void denom_kernel() {
    int wg = blockIdx.x * 8 + (threadIdx.x >> 5);   // wg = n*4+h
    int lane = threadIdx.x & 31;
    int h = wg & 3;
    size_t base = (size_t)wg * 256 + lane * 8;
    uint4 raw = *(const uint4*)&g_q[base];
    __nv_bfloat162* p = (__nv_bfloat162*)&raw;
    const float* ks = &g_ksum[h * 256 + lane * 8];
    float s = 0.f;
    #pragma unroll
    for (int i = 0; i < 4; i++) {
        float2 f = __bfloat1622float2(p[i]);
        s += f.x * ks[2 * i] + f.y * ks[2 * i + 1];
    }
    #pragma unroll
    for (int o = 16; o > 0; o >>= 1) s += __shfl_xor_sync(0xffffffffu, s, o);
    if (lane == 0) g_invden[wg] = 1.f / (s + 65536.f);
}

// ---------------- kv[h] = kn^T @ v, split-K partials -------------------------
__global__ __launch_bounds__(256) void kv_kernel() {
    __shared__ __nv_bfloat16 As2[32][136];  // [k(n)][m]
    __shared__ __nv_bfloat16 Bs[32][136];   // [k(n)][d]
    int tid = threadIdx.x, lane = tid & 31, warp = tid >> 5;
    int wm = (warp & 3) * 32, wn = (warp >> 2) * 64;
    int h = blockIdx.z >> 4;
    int chunk = blockIdx.z & 15;
    size_t n0 = (size_t)chunk * 4096;
    int m0 = blockIdx.y * 128, d0 = blockIdx.x * 128;
    int quad = lane >> 3, r8 = lane & 7;

    float acc[2][8][4];
    #pragma unroll
    for (int a = 0; a < 2; a++)
        #pragma unroll
        for (int b = 0; b < 8; b++)
            #pragma unroll
            for (int c = 0; c < 4; c++) acc[a][b][c] = 0.f;

    for (int kk = 0; kk < 4096; kk += 32) {
        int row = tid >> 4, seg = tid & 15;
        uint4 av0 = *(const uint4*)&g_k[(n0 + kk + row) * HD + h * 256 + m0 + seg * 8];
        uint4 av1 = *(const uint4*)&g_k[(n0 + kk + row + 16) * HD + h * 256 + m0 + seg * 8];
        uint4 bv0 = *(const uint4*)&g_v[(n0 + kk + row) * HD + h * 256 + d0 + seg * 8];
        uint4 bv1 = *(const uint4*)&g_v[(n0 + kk + row + 16) * HD + h * 256 + d0 + seg * 8];
        __syncthreads();
        *(uint4*)&As2[row][seg * 8] = av0;
        *(uint4*)&As2[row + 16][seg * 8] = av1;
        *(uint4*)&Bs[row][seg * 8] = bv0;
        *(uint4*)&Bs[row + 16][seg * 8] = bv1;
        __syncthreads();
        #pragma unroll
        for (int ks = 0; ks < 32; ks += 16) {
            uint32_t af[2][4], bf[4][4];
            #pragma unroll
            for (int mi = 0; mi < 2; mi++)   // A^T in smem -> ldmatrix.trans
                ldsm4t(af[mi], smem_u32(&As2[ks + (quad >> 1) * 8 + r8][wm + mi * 16 + (quad & 1) * 8]));
            #pragma unroll
            for (int nj = 0; nj < 4; nj++)
                ldsm4t(bf[nj], smem_u32(&Bs[ks + (quad & 1) * 8 + r8][wn + nj * 16 + (quad >> 1) * 8]));
            #pragma unroll
            for (int mi = 0; mi < 2; mi++)
                #pragma unroll
                for (int nj = 0; nj < 4; nj++) {
                    mma16816(acc[mi][2 * nj],     af[mi], &bf[nj][0]);
                    mma16816(acc[mi][2 * nj + 1], af[mi], &bf[nj][2]);
                }
        }
    }
    int group = lane >> 2, t4 = lane & 3;
    float* dst = &g_kv_part[(size_t)chunk * (4 * DIM * DIM) + h * (DIM * DIM)];
    #pragma unroll
    for (int mi = 0; mi < 2; mi++) {
        int rm = m0 + wm + mi * 16 + group;
        #pragma unroll
        for (int ni = 0; ni < 8; ni++) {
            int c = d0 + wn + ni * 8 + t4 * 2;
            *(float2*)&dst[rm * 256 + c]       = make_float2(acc[mi][ni][0], acc[mi][ni][1]);
            *(float2*)&dst[(rm + 8) * 256 + c] = make_float2(acc[mi][ni][2], acc[mi][ni][3]);
        }
    }
}

__global__ void kvred_kernel() {
    int i = blockIdx.x * 256 + threadIdx.x;   // grid = 1024 -> 262144
    float s = 0.f;
    #pragma unroll
    for (int p = 0; p < 16; p++) s += g_kv_part[p * (4 * DIM * DIM) + i];
    g_kvb[i] = __float2bfloat16(s);
}

// ---------------- out = 0.25 * sum_h (qn@kv + vsum) * invden -----------------
__global__ __launch_bounds__(256) void out_kernel(float* __restrict__ out) {
    __shared__ __nv_bfloat16 As[128][40];   // [n][k]
    __shared__ __nv_bfloat16 Bs[32][72];    // [k][d]
    int tid = threadIdx.x, lane = tid & 31, warp = tid >> 5;
    int wm = (warp & 3) * 32, wn = (warp >> 2) * 32;
    int d0 = blockIdx.x * 64;                  // grid.x = 4
    size_t r0 = (size_t)blockIdx.y * 128;      // grid.y = 512
    int quad = lane >> 3, r8 = lane & 7, group = lane >> 2, t4 = lane & 3;

    float accO[2][4][4];
    #pragma unroll
    for (int a = 0; a < 2; a++)
        #pragma unroll
        for (int b = 0; b < 4; b++)
            #pragma unroll
            for (int c = 0; c < 4; c++) accO[a][b][c] = 0.f;

    for (int h = 0; h < 4; h++) {
        float acc[2][4][4];
        #pragma unroll
        for (int a = 0; a < 2; a++)
            #pragma unroll
            for (int b = 0; b < 4; b++)
                #pragma unroll
                for (int c = 0; c < 4; c++) acc[a][b][c] = 0.f;

        for (int k0 = 0; k0 < 256; k0 += 32) {
            int rowa = tid >> 2, sega = tid & 3;
            uint4 av0 = *(const uint4*)&g_q[(r0 + rowa) * HD + h * 256 + k0 + sega * 8];
            uint4 av1 = *(const uint4*)&g_q[(r0 + rowa + 64) * HD + h * 256 + k0 + sega * 8];
            int rowb = tid >> 3, segb = tid & 7;
            uint4 bv0 = *(const uint4*)&g_kvb[h * (DIM * DIM) + (k0 + rowb) * 256 + d0 + segb * 8];
            __syncthreads();
            *(uint4*)&As[rowa][sega * 8] = av0;
            *(uint4*)&As[rowa + 64][sega * 8] = av1;
            *(uint4*)&Bs[rowb][segb * 8] = bv0;
            __syncthreads();
            #pragma unroll
            for (int ks = 0; ks < 32; ks += 16) {
                uint32_t af[2][4], bf2[2][4];
                #pragma unroll
                for (int mi = 0; mi < 2; mi++)
                    ldsm4(af[mi], smem_u32(&As[wm + mi * 16 + (quad & 1) * 8 + r8][ks + (quad >> 1) * 8]));
                #pragma unroll
                for (int nj = 0; nj < 2; nj++)
                    ldsm4t(bf2[nj], smem_u32(&Bs[ks + (quad & 1) * 8 + r8][wn + nj * 16 + (quad >> 1) * 8]));
                #pragma unroll
                for (int mi = 0; mi < 2; mi++)
                    #pragma unroll
                    for (int nj = 0; nj < 2; nj++) {
                        mma16816(acc[mi][2 * nj],     af[mi], &bf2[nj][0]);
                        mma16816(acc[mi][2 * nj + 1], af[mi], &bf2[nj][2]);
                    }
            }
        }
        #pragma unroll
        for (int mi = 0; mi < 2; mi++) {
            size_t rA = r0 + wm + mi * 16 + group;
            float ia = g_invden[rA * 4 + h];
            float ib = g_invden[(rA + 8) * 4 + h];
            #pragma unroll
            for (int ni = 0; ni < 4; ni++) {
                int c = d0 + wn + ni * 8 + t4 * 2;
                float vs0 = g_vsum[h * 256 + c], vs1 = g_vsum[h * 256 + c + 1];
                accO[mi][ni][0] += (acc[mi][ni][0] + vs0) * ia;
                accO[mi][ni][1] += (acc[mi][ni][1] + vs1) * ia;
                accO[mi][ni][2] += (acc[mi][ni][2] + vs0) * ib;
                accO[mi][ni][3] += (acc[mi][ni][3] + vs1) * ib;
            }
        }
    }
    #pragma unroll
    for (int mi = 0; mi < 2; mi++) {
        size_t rA = r0 + wm + mi * 16 + group;
        #pragma unroll
        for (int ni = 0; ni < 4; ni++) {
            int c = d0 + wn + ni * 8 + t4 * 2;
            *(float2*)&out[rA * 256 + c] =
                make_float2(accO[mi][ni][0] * 0.25f, accO[mi][ni][1] * 0.25f);
            *(float2*)&out[(rA + 8) * 256 + c] =
                make_float2(accO[mi][ni][2] * 0.25f, accO[mi][ni][3] * 0.25f);
        }
    }
}

// ---------------- launch -----------------------------------------------------
extern "C" void kernel_launch(void* const* d_in, const int* in_sizes, int n_in,
                              void* d_out, int out_size) {
    const float* x  = (const float*)d_in[0];
    const float* Wq = (const float*)d_in[1];
    const float* bq = (const float*)d_in[2];
    const float* Wk = (const float*)d_in[3];
    const float* bk = (const float*)d_in[4];
    const float* Wv = (const float*)d_in[5];
    const float* bv = (const float*)d_in[6];
    float* out = (float*)d_out;

    cvt_x_kernel<<<2048, 256>>>(x);
    cvt_w_kernel<<<512, 256>>>(Wq, 0);
    cvt_w_kernel<<<512, 256>>>(Wk, 1);
    cvt_w_kernel<<<512, 256>>>(Wv, 2);

    colsum_p_kernel<<<dim3(2, 64), 256>>>(x);
    colsum_red_kernel<<<2, 256>>>();
    vsum_kernel<<<1, 1024>>>(Wv, bv);

    proj_kernel<<<dim3(8, 512), 256>>>(0, bq);
    proj_kernel<<<dim3(8, 512), 256>>>(1, bk);
    proj_kernel<<<dim3(8, 512), 256>>>(2, bv);

    norm_kernel<<<32768, 256>>>(0);   // qn
    norm_kernel<<<32768, 256>>>(1);   // kn

    ksum_p_kernel<<<dim3(4, 64), 256>>>();
    ksum_red_kernel<<<4, 256>>>();
    denom_kernel<<<32768, 256>>>();

    kv_kernel<<<dim3(2, 2, 64), 256>>>();
    kvred_kernel<<<1024, 256>>>();

    out_kernel<<<dim3(4, 512), 256>>>(out);
}

// round 2
// speedup vs baseline: 1.0923x; 1.0923x over previous
#include <cuda_runtime.h>
#include <cuda_bf16.h>
#include <cstdint>

#define NN   65536
#define INC  512
#define HD   1024
#define DIM  256

// ---------------- scratch (device globals) -----------------------------------
__device__ __nv_bfloat16 g_xb[NN * INC];
__device__ __nv_bfloat16 g_wb[3][INC * HD];
__device__ __nv_bfloat16 g_q[NN * HD];
__device__ __nv_bfloat16 g_k[NN * HD];
__device__ __nv_bfloat16 g_v[NN * HD];
__device__ float g_colsum_p[128 * INC];
__device__ float g_colsum[INC];
__device__ float g_vsum[HD];
__device__ float g_ksum_p[64 * HD];
__device__ float g_ksum[HD];
__device__ float g_kv_part[16 * 4 * DIM * DIM];
__device__ __nv_bfloat16 g_kvb[4 * DIM * DIM];   // stacked [h*256+m][256]
__device__ float g_invden[NN * 4];

// ---------------- helpers ----------------------------------------------------
__device__ __forceinline__ uint32_t smem_u32(const void* p) {
    return (uint32_t)__cvta_generic_to_shared(p);
}
__device__ __forceinline__ void ldsm4(uint32_t* r, uint32_t a) {
    asm volatile("ldmatrix.sync.aligned.m8n8.x4.shared.b16 {%0,%1,%2,%3}, [%4];"
        : "=r"(r[0]), "=r"(r[1]), "=r"(r[2]), "=r"(r[3]) : "r"(a));
}
__device__ __forceinline__ void ldsm4t(uint32_t* r, uint32_t a) {
    asm volatile("ldmatrix.sync.aligned.m8n8.x4.trans.shared.b16 {%0,%1,%2,%3}, [%4];"
        : "=r"(r[0]), "=r"(r[1]), "=r"(r[2]), "=r"(r[3]) : "r"(a));
}
__device__ __forceinline__ void mma16816(float* d, const uint32_t* a, const uint32_t* b) {
    asm volatile("mma.sync.aligned.m16n8k16.row.col.f32.bf16.bf16.f32 "
        "{%0,%1,%2,%3}, {%4,%5,%6,%7}, {%8,%9}, {%0,%1,%2,%3};"
        : "+f"(d[0]), "+f"(d[1]), "+f"(d[2]), "+f"(d[3])
        : "r"(a[0]), "r"(a[1]), "r"(a[2]), "r"(a[3]), "r"(b[0]), "r"(b[1]));
}
__device__ __forceinline__ void cp16(void* s, const void* g) {
    asm volatile("cp.async.cg.shared.global [%0], [%1], 16;"
        :: "r"(smem_u32(s)), "l"(g));
}
__device__ __forceinline__ void cp_commit() { asm volatile("cp.async.commit_group;"); }
template<int W> __device__ __forceinline__ void cp_wait() {
    asm volatile("cp.async.wait_group %0;" :: "n"(W));
}

// ---------------- cvt_x + colsum partials (fused) ----------------------------
__global__ void cvt_x_kernel(const float* __restrict__ x) {
    int p = blockIdx.x;                 // 64 blocks, 1024 rows each
    int tid = threadIdx.x;              // 256
    int seg = tid & 127, half = tid >> 7;
    size_t r0 = (size_t)p * 1024;
    float c0 = 0.f, c1 = 0.f, c2 = 0.f, c3 = 0.f;
    for (int i = half; i < 1024; i += 2) {
        float4 f = ((const float4*)x)[(r0 + i) * 128 + seg];
        c0 += f.x; c1 += f.y; c2 += f.z; c3 += f.w;
        __nv_bfloat162* d = (__nv_bfloat162*)g_xb + (r0 + i) * 256 + seg * 2;
        d[0] = __floats2bfloat162_rn(f.x, f.y);
        d[1] = __floats2bfloat162_rn(f.z, f.w);
    }
    float* dst = &g_colsum_p[(p * 2 + half) * INC + seg * 4];
    dst[0] = c0; dst[1] = c1; dst[2] = c2; dst[3] = c3;
}
__global__ void colsum_red_kernel() {
    int c = blockIdx.x * 256 + threadIdx.x;     // grid.x = 2
    float s = 0.f;
    for (int p = 0; p < 128; p++) s += g_colsum_p[p * INC + c];
    g_colsum[c] = s;
}
__global__ void vsum_kernel(const float* __restrict__ Wv, const float* __restrict__ bv) {
    int m = threadIdx.x;                         // 1024
    float s = 0.f;
    for (int kk = 0; kk < INC; kk++) s += g_colsum[kk] * Wv[kk * HD + m];
    g_vsum[m] = s + 65536.f * bv[m];
}

__global__ void cvt_w_kernel(const float* __restrict__ Wq,
                             const float* __restrict__ Wk,
                             const float* __restrict__ Wv) {
    int which = blockIdx.y;
    const float* src = which == 0 ? Wq : which == 1 ? Wk : Wv;
    int i = blockIdx.x * 256 + threadIdx.x;      // grid.x = 512 -> exactly 131072
    float4 f = ((const float4*)src)[i];
    __nv_bfloat162* d2 = (__nv_bfloat162*)g_wb[which];
    d2[2 * i]     = __floats2bfloat162_rn(f.x, f.y);
    d2[2 * i + 1] = __floats2bfloat162_rn(f.z, f.w);
}

// ---------------- fused QKV GEMM + bias + (q,k) L2-normalize -----------------
// tile 128x256, 512 threads, k=64 double-buffered cp.async
#define APITCH 72
#define BPITCH 264
#define ASTG (128 * APITCH)
#define BSTG (64 * BPITCH)
#define GEMM_SMEM_BYTES ((2 * (ASTG + BSTG)) * 2)

__global__ __launch_bounds__(512) void qkv_kernel(const float* __restrict__ bq,
                                                  const float* __restrict__ bk,
                                                  const float* __restrict__ bv) {
    extern __shared__ __nv_bfloat16 sm[];
    __nv_bfloat16* As = sm;                  // [2][128][APITCH]
    __nv_bfloat16* Bs = sm + 2 * ASTG;       // [2][64][BPITCH]

    int which = blockIdx.x >> 2;
    int n0 = (blockIdx.x & 3) * 256;
    size_t r0 = (size_t)blockIdx.y * 128;
    const __nv_bfloat16* __restrict__ B = g_wb[which];
    __nv_bfloat16* __restrict__ C = which == 0 ? g_q : which == 1 ? g_k : g_v;
    const float* __restrict__ bias = which == 0 ? bq : which == 1 ? bk : bv;

    int tid = threadIdx.x, lane = tid & 31, warp = tid >> 5;
    int wm = (warp & 3) * 32, wn = (warp >> 2) * 64;
    int quad = lane >> 3, r8 = lane & 7;
    int arow = tid >> 3, aseg = tid & 7;
    int brow = tid >> 5, bseg = tid & 31;

    float acc[2][8][4];
    #pragma unroll
    for (int a = 0; a < 2; a++)
        #pragma unroll
        for (int b = 0; b < 8; b++)
            #pragma unroll
            for (int c = 0; c < 4; c++) acc[a][b][c] = 0.f;

    auto load_stage = [&](int st, int k0) {
        #pragma unroll
        for (int rr = 0; rr < 2; rr++)
            cp16(&As[st * ASTG + (arow + rr * 64) * APITCH + aseg * 8],
                 &g_xb[(r0 + arow + rr * 64) * INC + k0 + aseg * 8]);
        #pragma unroll
        for (int rr = 0; rr < 4; rr++)
            cp16(&Bs[st * BSTG + (brow + rr * 16) * BPITCH + bseg * 8],
                 &B[(size_t)(k0 + brow + rr * 16) * HD + n0 + bseg * 8]);
        cp_commit();
    };

    load_stage(0, 0);
    #pragma unroll 1
    for (int it = 0; it < 8; it++) {
        int st = it & 1;
        if (it < 7) { load_stage(st ^ 1, (it + 1) * 64); cp_wait<1>(); }
        else        { cp_wait<0>(); }
        __syncthreads();
        #pragma unroll
        for (int ks = 0; ks < 64; ks += 16) {
            uint32_t af[2][4], bf[4][4];
            #pragma unroll
            for (int mi = 0; mi < 2; mi++)
                ldsm4(af[mi], smem_u32(&As[st * ASTG +
                    (wm + mi * 16 + (quad & 1) * 8 + r8) * APITCH + ks + (quad >> 1) * 8]));
            #pragma unroll
            for (int nj = 0; nj < 4; nj++)
                ldsm4t(bf[nj], smem_u32(&Bs[st * BSTG +
                    (ks + (quad & 1) * 8 + r8) * BPITCH + wn + nj * 16 + (quad >> 1) * 8]));
            #pragma unroll
            for (int mi = 0; mi < 2; mi++)
                #pragma unroll
                for (int nj = 0; nj < 4; nj++) {
                    mma16816(acc[mi][2 * nj],     af[mi], &bf[nj][0]);
                    mma16816(acc[mi][2 * nj + 1], af[mi], &bf[nj][2]);
                }
        }
        __syncthreads();
    }

    int group = lane >> 2, t4 = lane & 3;
    // bias + sumsq
    float ss0[2] = {0.f, 0.f}, ss1[2] = {0.f, 0.f};
    #pragma unroll
    for (int mi = 0; mi < 2; mi++)
        #pragma unroll
        for (int ni = 0; ni < 8; ni++) {
            int c = n0 + wn + ni * 8 + t4 * 2;
            float b0 = __ldg(&bias[c]), b1 = __ldg(&bias[c + 1]);
            acc[mi][ni][0] += b0; acc[mi][ni][1] += b1;
            acc[mi][ni][2] += b0; acc[mi][ni][3] += b1;
            ss0[mi] += acc[mi][ni][0] * acc[mi][ni][0] + acc[mi][ni][1] * acc[mi][ni][1];
            ss1[mi] += acc[mi][ni][2] * acc[mi][ni][2] + acc[mi][ni][3] * acc[mi][ni][3];
        }

    if (which < 2) {   // normalize q,k rows (tile == one full head)
        #pragma unroll
        for (int mi = 0; mi < 2; mi++) {
            ss0[mi] += __shfl_xor_sync(0xffffffffu, ss0[mi], 1);
            ss0[mi] += __shfl_xor_sync(0xffffffffu, ss0[mi], 2);
            ss1[mi] += __shfl_xor_sync(0xffffffffu, ss1[mi], 1);
            ss1[mi] += __shfl_xor_sync(0xffffffffu, ss1[mi], 2);
        }
        float* ssbuf = (float*)sm;   // [4][128], smem reuse (loop ended with sync)
        int wnid = warp >> 2;
        if (t4 == 0) {
            #pragma unroll
            for (int mi = 0; mi < 2; mi++) {
                ssbuf[wnid * 128 + wm + mi * 16 + group]     = ss0[mi];
                ssbuf[wnid * 128 + wm + mi * 16 + group + 8] = ss1[mi];
            }
        }
        __syncthreads();
        #pragma unroll
        for (int mi = 0; mi < 2; mi++) {
            int ra = wm + mi * 16 + group;
            float s0 = ssbuf[ra] + ssbuf[128 + ra] + ssbuf[256 + ra] + ssbuf[384 + ra];
            int rb = ra + 8;
            float s1 = ssbuf[rb] + ssbuf[128 + rb] + ssbuf[256 + rb] + ssbuf[384 + rb];
            float i0 = rsqrtf(s0), i1 = rsqrtf(s1);
            #pragma unroll
            for (int ni = 0; ni < 8; ni++) {
                acc[mi][ni][0] *= i0; acc[mi][ni][1] *= i0;
                acc[mi][ni][2] *= i1; acc[mi][ni][3] *= i1;
            }
        }
    }

    #pragma unroll
    for (int mi = 0; mi < 2; mi++) {
        size_t rA = r0 + wm + mi * 16 + group;
        #pragma unroll
        for (int ni = 0; ni < 8; ni++) {
            int c = n0 + wn + ni * 8 + t4 * 2;
            *(__nv_bfloat162*)&C[rA * HD + c] =
                __floats2bfloat162_rn(acc[mi][ni][0], acc[mi][ni][1]);
            *(__nv_bfloat162*)&C[(rA + 8) * HD + c] =
                __floats2bfloat162_rn(acc[mi][ni][2], acc[mi][ni][3]);
        }
    }
}

// ---------------- ksum (column sums of kn) -----------------------------------
__global__ void ksum_p_kernel() {
    int c = blockIdx.x * 256 + threadIdx.x;   // grid.x = 4
    int p = blockIdx.y;                        // grid.y = 64
    size_t r0 = (size_t)p * 1024;
    float s = 0.f;
    for (int r = 0; r < 1024; r++) s += __bfloat162float(g_k[(r0 + r) * HD + c]);
    g_ksum_p[p * HD + c] = s;
}
__global__ void ksum_red_kernel() {
    int c = blockIdx.x * 256 + threadIdx.x;   // grid.x = 4
    float s = 0.f;
    for (int p = 0; p < 64; p++) s += g_ksum_p[p * HD + c];
    g_ksum[c] = s;
}

// ---------------- invden + in-place q scaling --------------------------------
__global__ void denom_scale_kernel() {
    int wg = blockIdx.x * 8 + (threadIdx.x >> 5);   // wg = n*4+h
    int lane = threadIdx.x & 31, h = wg & 3;
    size_t base = (size_t)wg * 256 + lane * 8;
    uint4 raw = *(const uint4*)&g_q[base];
    __nv_bfloat162* p = (__nv_bfloat162*)&raw;
    const float* ks = &g_ksum[h * 256 + lane * 8];
    float s = 0.f;
    float2 f[4];
    #pragma unroll
    for (int i = 0; i < 4; i++) {
        f[i] = __bfloat1622float2(p[i]);
        s += f[i].x * ks[2 * i] + f[i].y * ks[2 * i + 1];
    }
    #pragma unroll
    for (int o = 16; o > 0; o >>= 1) s += __shfl_xor_sync(0xffffffffu, s, o);
    float inv = 1.f / (s + 65536.f);
    #pragma unroll
    for (int i = 0; i < 4; i++)
        p[i] = __floats2bfloat162_rn(f[i].x * inv, f[i].y * inv);
    *(uint4*)&g_q[base] = raw;
    if (lane == 0) g_invden[wg] = inv;
}

// ---------------- kv[h] = kn^T @ v, split-K ----------------------------------
__global__ __launch_bounds__(256) void kv_kernel() {
    __shared__ __nv_bfloat16 As2[32][136];
    __shared__ __nv_bfloat16 Bs[32][136];
    int tid = threadIdx.x, lane = tid & 31, warp = tid >> 5;
    int wm = (warp & 3) * 32, wn = (warp >> 2) * 64;
    int h = blockIdx.z >> 4;
    int chunk = blockIdx.z & 15;
    size_t n0 = (size_t)chunk * 4096;
    int m0 = blockIdx.y * 128, d0 = blockIdx.x * 128;
    int quad = lane >> 3, r8 = lane & 7;

    float acc[2][8][4];
    #pragma unroll
    for (int a = 0; a < 2; a++)
        #pragma unroll
        for (int b = 0; b < 8; b++)
            #pragma unroll
            for (int c = 0; c < 4; c++) acc[a][b][c] = 0.f;

    for (int kk = 0; kk < 4096; kk += 32) {
        int row = tid >> 4, seg = tid & 15;
        uint4 av0 = *(const uint4*)&g_k[(n0 + kk + row) * HD + h * 256 + m0 + seg * 8];
        uint4 av1 = *(const uint4*)&g_k[(n0 + kk + row + 16) * HD + h * 256 + m0 + seg * 8];
        uint4 bv0 = *(const uint4*)&g_v[(n0 + kk + row) * HD + h * 256 + d0 + seg * 8];
        uint4 bv1 = *(const uint4*)&g_v[(n0 + kk + row + 16) * HD + h * 256 + d0 + seg * 8];
        __syncthreads();
        *(uint4*)&As2[row][seg * 8] = av0;
        *(uint4*)&As2[row + 16][seg * 8] = av1;
        *(uint4*)&Bs[row][seg * 8] = bv0;
        *(uint4*)&Bs[row + 16][seg * 8] = bv1;
        __syncthreads();
        #pragma unroll
        for (int ks = 0; ks < 32; ks += 16) {
            uint32_t af[2][4], bf[4][4];
            #pragma unroll
            for (int mi = 0; mi < 2; mi++)
                ldsm4t(af[mi], smem_u32(&As2[ks + (quad >> 1) * 8 + r8][wm + mi * 16 + (quad & 1) * 8]));
            #pragma unroll
            for (int nj = 0; nj < 4; nj++)
                ldsm4t(bf[nj], smem_u32(&Bs[ks + (quad & 1) * 8 + r8][wn + nj * 16 + (quad >> 1) * 8]));
            #pragma unroll
            for (int mi = 0; mi < 2; mi++)
                #pragma unroll
                for (int nj = 0; nj < 4; nj++) {
                    mma16816(acc[mi][2 * nj],     af[mi], &bf[nj][0]);
                    mma16816(acc[mi][2 * nj + 1], af[mi], &bf[nj][2]);
                }
        }
    }
    int group = lane >> 2, t4 = lane & 3;
    float* dst = &g_kv_part[(size_t)chunk * (4 * DIM * DIM) + h * (DIM * DIM)];
    #pragma unroll
    for (int mi = 0; mi < 2; mi++) {
        int rm = m0 + wm + mi * 16 + group;
        #pragma unroll
        for (int ni = 0; ni < 8; ni++) {
            int c = d0 + wn + ni * 8 + t4 * 2;
            *(float2*)&dst[rm * 256 + c]       = make_float2(acc[mi][ni][0], acc[mi][ni][1]);
            *(float2*)&dst[(rm + 8) * 256 + c] = make_float2(acc[mi][ni][2], acc[mi][ni][3]);
        }
    }
}

__global__ void kvred_kernel() {
    int i = blockIdx.x * 256 + threadIdx.x;
    float s = 0.f;
    #pragma unroll
    for (int p = 0; p < 16; p++) s += g_kv_part[p * (4 * DIM * DIM) + i];
    g_kvb[i] = __float2bfloat16(s);
}

// ---------------- out = 0.25*(q' @ kv_stacked + rowoff), K=1024 --------------
__global__ __launch_bounds__(512) void out_kernel(float* __restrict__ out) {
    extern __shared__ __nv_bfloat16 sm[];
    __nv_bfloat16* As = sm;
    __nv_bfloat16* Bs = sm + 2 * ASTG;

    size_t r0 = (size_t)blockIdx.y * 128;
    int tid = threadIdx.x, lane = tid & 31, warp = tid >> 5;
    int wm = (warp & 3) * 32, wn = (warp >> 2) * 64;
    int quad = lane >> 3, r8 = lane & 7;
    int arow = tid >> 3, aseg = tid & 7;
    int brow = tid >> 5, bseg = tid & 31;

    float acc[2][8][4];
    #pragma unroll
    for (int a = 0; a < 2; a++)
        #pragma unroll
        for (int b = 0; b < 8; b++)
            #pragma unroll
            for (int c = 0; c < 4; c++) acc[a][b][c] = 0.f;

    auto load_stage = [&](int st, int k0) {
        #pragma unroll
        for (int rr = 0; rr < 2; rr++)
            cp16(&As[st * ASTG + (arow + rr * 64) * APITCH + aseg * 8],
                 &g_q[(r0 + arow + rr * 64) * HD + k0 + aseg * 8]);
        #pragma unroll
        for (int rr = 0; rr < 4; rr++)
            cp16(&Bs[st * BSTG + (brow + rr * 16) * BPITCH + bseg * 8],
                 &g_kvb[(size_t)(k0 + brow + rr * 16) * 256 + bseg * 8]);
        cp_commit();
    };

    load_stage(0, 0);
    #pragma unroll 1
    for (int it = 0; it < 16; it++) {
        int st = it & 1;
        if (it < 15) { load_stage(st ^ 1, (it + 1) * 64); cp_wait<1>(); }
        else         { cp_wait<0>(); }
        __syncthreads();
        #pragma unroll
        for (int ks = 0; ks < 64; ks += 16) {
            uint32_t af[2][4], bf[4][4];
            #pragma unroll
            for (int mi = 0; mi < 2; mi++)
                ldsm4(af[mi], smem_u32(&As[st * ASTG +
                    (wm + mi * 16 + (quad & 1) * 8 + r8) * APITCH + ks + (quad >> 1) * 8]));
            #pragma unroll
            for (int nj = 0; nj < 4; nj++)
                ldsm4t(bf[nj], smem_u32(&Bs[st * BSTG +
                    (ks + (quad & 1) * 8 + r8) * BPITCH + wn + nj * 16 + (quad >> 1) * 8]));
            #pragma unroll
            for (int mi = 0; mi < 2; mi++)
                #pragma unroll
                for (int nj = 0; nj < 4; nj++) {
                    mma16816(acc[mi][2 * nj],     af[mi], &bf[nj][0]);
                    mma16816(acc[mi][2 * nj + 1], af[mi], &bf[nj][2]);
                }
        }
        __syncthreads();
    }

    int group = lane >> 2, t4 = lane & 3;
    #pragma unroll
    for (int mi = 0; mi < 2; mi++) {
        size_t rA = r0 + wm + mi * 16 + group;
        size_t rB = rA + 8;
        float ia[4], ib[4];
        #pragma unroll
        for (int h = 0; h < 4; h++) {
            ia[h] = g_invden[rA * 4 + h];
            ib[h] = g_invden[rB * 4 + h];
        }
        #pragma unroll
        for (int ni = 0; ni < 8; ni++) {
            int c = wn + ni * 8 + t4 * 2;
            float roa0 = 0.f, roa1 = 0.f, rob0 = 0.f, rob1 = 0.f;
            #pragma unroll
            for (int h = 0; h < 4; h++) {
                float v0 = __ldg(&g_vsum[h * 256 + c]);
                float v1 = __ldg(&g_vsum[h * 256 + c + 1]);
                roa0 += ia[h] * v0; roa1 += ia[h] * v1;
                rob0 += ib[h] * v0; rob1 += ib[h] * v1;
            }
            *(float2*)&out[rA * 256 + c] =
                make_float2(0.25f * (acc[mi][ni][0] + roa0), 0.25f * (acc[mi][ni][1] + roa1));
            *(float2*)&out[rB * 256 + c] =
                make_float2(0.25f * (acc[mi][ni][2] + rob0), 0.25f * (acc[mi][ni][3] + rob1));
        }
    }
}

// ---------------- launch -----------------------------------------------------
extern "C" void kernel_launch(void* const* d_in, const int* in_sizes, int n_in,
                              void* d_out, int out_size) {
    const float* x  = (const float*)d_in[0];
    const float* Wq = (const float*)d_in[1];
    const float* bq = (const float*)d_in[2];
    const float* Wk = (const float*)d_in[3];
    const float* bk = (const float*)d_in[4];
    const float* Wv = (const float*)d_in[5];
    const float* bv = (const float*)d_in[6];
    float* out = (float*)d_out;

    cudaFuncSetAttribute(qkv_kernel, cudaFuncAttributeMaxDynamicSharedMemorySize, GEMM_SMEM_BYTES);
    cudaFuncSetAttribute(out_kernel, cudaFuncAttributeMaxDynamicSharedMemorySize, GEMM_SMEM_BYTES);

    cvt_x_kernel<<<64, 256>>>(x);
    cvt_w_kernel<<<dim3(512, 3), 256>>>(Wq, Wk, Wv);
    colsum_red_kernel<<<2, 256>>>();
    vsum_kernel<<<1, 1024>>>(Wv, bv);

    qkv_kernel<<<dim3(12, 512), 512, GEMM_SMEM_BYTES>>>(bq, bk, bv);

    ksum_p_kernel<<<dim3(4, 64), 256>>>();
    ksum_red_kernel<<<4, 256>>>();
    denom_scale_kernel<<<32768, 256>>>();

    kv_kernel<<<dim3(2, 2, 64), 256>>>();
    kvred_kernel<<<1024, 256>>>();

    out_kernel<<<dim3(1, 512), 512, GEMM_SMEM_BYTES>>>(out);
}

// round 3
// speedup vs baseline: 1.2111x; 1.1088x over previous
#include <cuda_runtime.h>
#include <cuda_bf16.h>
#include <cstdint>

#define NN   65536
#define INC  512
#define HD   1024
#define DIM  256

// ---------------- scratch (device globals) -----------------------------------
__device__ __nv_bfloat16 g_xb[NN * INC];
__device__ __nv_bfloat16 g_wb[3][INC * HD];
__device__ __nv_bfloat16 g_q[NN * HD];
__device__ __nv_bfloat16 g_k[NN * HD];
__device__ __nv_bfloat16 g_v[NN * HD];
__device__ float g_colsum_p[512 * INC];
__device__ float g_colsum[INC];
__device__ float g_vsum[HD];
__device__ float g_ksum_p[64 * HD];
__device__ float g_ksum[HD];
__device__ float g_kv_part[16 * 4 * DIM * DIM];
__device__ __nv_bfloat16 g_kvb[4 * DIM * DIM];   // stacked [h*256+m][256]
__device__ float g_invden[NN * 4];

// ---------------- helpers ----------------------------------------------------
__device__ __forceinline__ uint32_t smem_u32(const void* p) {
    return (uint32_t)__cvta_generic_to_shared(p);
}
__device__ __forceinline__ void ldsm4(uint32_t* r, uint32_t a) {
    asm volatile("ldmatrix.sync.aligned.m8n8.x4.shared.b16 {%0,%1,%2,%3}, [%4];"
        : "=r"(r[0]), "=r"(r[1]), "=r"(r[2]), "=r"(r[3]) : "r"(a));
}
__device__ __forceinline__ void ldsm4t(uint32_t* r, uint32_t a) {
    asm volatile("ldmatrix.sync.aligned.m8n8.x4.trans.shared.b16 {%0,%1,%2,%3}, [%4];"
        : "=r"(r[0]), "=r"(r[1]), "=r"(r[2]), "=r"(r[3]) : "r"(a));
}
__device__ __forceinline__ void mma16816(float* d, const uint32_t* a, const uint32_t* b) {
    asm volatile("mma.sync.aligned.m16n8k16.row.col.f32.bf16.bf16.f32 "
        "{%0,%1,%2,%3}, {%4,%5,%6,%7}, {%8,%9}, {%0,%1,%2,%3};"
        : "+f"(d[0]), "+f"(d[1]), "+f"(d[2]), "+f"(d[3])
        : "r"(a[0]), "r"(a[1]), "r"(a[2]), "r"(a[3]), "r"(b[0]), "r"(b[1]));
}
__device__ __forceinline__ void cp16(void* s, const void* g) {
    asm volatile("cp.async.cg.shared.global [%0], [%1], 16;"
        :: "r"(smem_u32(s)), "l"(g));
}
__device__ __forceinline__ void cp_commit() { asm volatile("cp.async.commit_group;"); }
template<int W> __device__ __forceinline__ void cp_wait() {
    asm volatile("cp.async.wait_group %0;" :: "n"(W));
}

// ---------------- cvt_x + colsum partials (fused) ----------------------------
__global__ void cvt_x_kernel(const float* __restrict__ x) {
    int p = blockIdx.x;                 // 256 blocks, 256 rows each
    int tid = threadIdx.x;              // 256
    int seg = tid & 127, half = tid >> 7;
    size_t r0 = (size_t)p * 256;
    float c0 = 0.f, c1 = 0.f, c2 = 0.f, c3 = 0.f;
    for (int i = half; i < 256; i += 2) {
        float4 f = ((const float4*)x)[(r0 + i) * 128 + seg];
        c0 += f.x; c1 += f.y; c2 += f.z; c3 += f.w;
        __nv_bfloat162* d = (__nv_bfloat162*)g_xb + (r0 + i) * 256 + seg * 2;
        d[0] = __floats2bfloat162_rn(f.x, f.y);
        d[1] = __floats2bfloat162_rn(f.z, f.w);
    }
    float* dst = &g_colsum_p[(p * 2 + half) * INC + seg * 4];
    dst[0] = c0; dst[1] = c1; dst[2] = c2; dst[3] = c3;
}
__global__ void colsum_red_kernel() {
    int c = blockIdx.x * 256 + threadIdx.x;     // grid.x = 2
    float s = 0.f;
    for (int p = 0; p < 512; p++) s += g_colsum_p[p * INC + c];
    g_colsum[c] = s;
}
__global__ void vsum_kernel(const float* __restrict__ Wv, const float* __restrict__ bv) {
    int warp = threadIdx.x >> 5, lane = threadIdx.x & 31;
    int m = blockIdx.x * 8 + warp;               // grid = 128, block = 256
    float s = 0.f;
    for (int kk = lane; kk < INC; kk += 32) s += g_colsum[kk] * Wv[kk * HD + m];
    #pragma unroll
    for (int o = 16; o > 0; o >>= 1) s += __shfl_xor_sync(0xffffffffu, s, o);
    if (lane == 0) g_vsum[m] = s + 65536.f * bv[m];
}

__global__ void cvt_w_kernel(const float* __restrict__ Wq,
                             const float* __restrict__ Wk,
                             const float* __restrict__ Wv) {
    int which = blockIdx.y;
    const float* src = which == 0 ? Wq : which == 1 ? Wk : Wv;
    int i = blockIdx.x * 256 + threadIdx.x;      // grid.x = 512
    float4 f = ((const float4*)src)[i];
    __nv_bfloat162* d2 = (__nv_bfloat162*)g_wb[which];
    d2[2 * i]     = __floats2bfloat162_rn(f.x, f.y);
    d2[2 * i + 1] = __floats2bfloat162_rn(f.z, f.w);
}

// ---------------- fused QKV GEMM + bias + (q,k) L2-normalize -----------------
// tile 128x256, 512 threads, k=64, 3-stage cp.async, one sync per stage
#define APITCH 72
#define BPITCH 264
#define ASTG (128 * APITCH)
#define BSTG (64 * BPITCH)
#define GEMM_SMEM_BYTES ((3 * (ASTG + BSTG)) * 2)

__global__ __launch_bounds__(512) void qkv_kernel(const float* __restrict__ bq,
                                                  const float* __restrict__ bk,
                                                  const float* __restrict__ bv) {
    extern __shared__ __nv_bfloat16 sm[];
    __nv_bfloat16* As = sm;                  // [3][128][APITCH]
    __nv_bfloat16* Bs = sm + 3 * ASTG;       // [3][64][BPITCH]

    int which = blockIdx.x >> 2;
    int n0 = (blockIdx.x & 3) * 256;
    size_t r0 = (size_t)blockIdx.y * 128;
    const __nv_bfloat16* __restrict__ B = g_wb[which];
    __nv_bfloat16* __restrict__ C = which == 0 ? g_q : which == 1 ? g_k : g_v;
    const float* __restrict__ bias = which == 0 ? bq : which == 1 ? bk : bv;

    int tid = threadIdx.x, lane = tid & 31, warp = tid >> 5;
    int wm = (warp & 3) * 32, wn = (warp >> 2) * 64;
    int quad = lane >> 3, r8 = lane & 7;
    int arow = tid >> 3, aseg = tid & 7;
    int brow = tid >> 5, bseg = tid & 31;

    float acc[2][8][4];
    #pragma unroll
    for (int a = 0; a < 2; a++)
        #pragma unroll
        for (int b = 0; b < 8; b++)
            #pragma unroll
            for (int c = 0; c < 4; c++) acc[a][b][c] = 0.f;

    auto load_stage = [&](int st, int k0) {
        #pragma unroll
        for (int rr = 0; rr < 2; rr++)
            cp16(&As[st * ASTG + (arow + rr * 64) * APITCH + aseg * 8],
                 &g_xb[(r0 + arow + rr * 64) * INC + k0 + aseg * 8]);
        #pragma unroll
        for (int rr = 0; rr < 4; rr++)
            cp16(&Bs[st * BSTG + (brow + rr * 16) * BPITCH + bseg * 8],
                 &B[(size_t)(k0 + brow + rr * 16) * HD + n0 + bseg * 8]);
        cp_commit();
    };

    load_stage(0, 0);
    load_stage(1, 64);
    #pragma unroll 1
    for (int it = 0; it < 8; it++) {
        int st = it % 3;
        if (it < 7) cp_wait<1>(); else cp_wait<0>();
        __syncthreads();
        if (it + 2 < 8) load_stage((it + 2) % 3, (it + 2) * 64);
        #pragma unroll
        for (int ks = 0; ks < 64; ks += 16) {
            uint32_t af[2][4], bf[4][4];
            #pragma unroll
            for (int mi = 0; mi < 2; mi++)
                ldsm4(af[mi], smem_u32(&As[st * ASTG +
                    (wm + mi * 16 + (quad & 1) * 8 + r8) * APITCH + ks + (quad >> 1) * 8]));
            #pragma unroll
            for (int nj = 0; nj < 4; nj++)
                ldsm4t(bf[nj], smem_u32(&Bs[st * BSTG +
                    (ks + (quad & 1) * 8 + r8) * BPITCH + wn + nj * 16 + (quad >> 1) * 8]));
            #pragma unroll
            for (int mi = 0; mi < 2; mi++)
                #pragma unroll
                for (int nj = 0; nj < 4; nj++) {
                    mma16816(acc[mi][2 * nj],     af[mi], &bf[nj][0]);
                    mma16816(acc[mi][2 * nj + 1], af[mi], &bf[nj][2]);
                }
        }
    }

    int group = lane >> 2, t4 = lane & 3;
    float ss0[2] = {0.f, 0.f}, ss1[2] = {0.f, 0.f};
    #pragma unroll
    for (int mi = 0; mi < 2; mi++)
        #pragma unroll
        for (int ni = 0; ni < 8; ni++) {
            int c = n0 + wn + ni * 8 + t4 * 2;
            float b0 = __ldg(&bias[c]), b1 = __ldg(&bias[c + 1]);
            acc[mi][ni][0] += b0; acc[mi][ni][1] += b1;
            acc[mi][ni][2] += b0; acc[mi][ni][3] += b1;
            ss0[mi] += acc[mi][ni][0] * acc[mi][ni][0] + acc[mi][ni][1] * acc[mi][ni][1];
            ss1[mi] += acc[mi][ni][2] * acc[mi][ni][2] + acc[mi][ni][3] * acc[mi][ni][3];
        }

    if (which < 2) {   // normalize q,k rows (tile == one full head)
        #pragma unroll
        for (int mi = 0; mi < 2; mi++) {
            ss0[mi] += __shfl_xor_sync(0xffffffffu, ss0[mi], 1);
            ss0[mi] += __shfl_xor_sync(0xffffffffu, ss0[mi], 2);
            ss1[mi] += __shfl_xor_sync(0xffffffffu, ss1[mi], 1);
            ss1[mi] += __shfl_xor_sync(0xffffffffu, ss1[mi], 2);
        }
        float* ssbuf = (float*)sm;   // stage-0 A region; last read 2 iters ago
        int wnid = warp >> 2;
        if (t4 == 0) {
            #pragma unroll
            for (int mi = 0; mi < 2; mi++) {
                ssbuf[wnid * 128 + wm + mi * 16 + group]     = ss0[mi];
                ssbuf[wnid * 128 + wm + mi * 16 + group + 8] = ss1[mi];
            }
        }
        __syncthreads();
        #pragma unroll
        for (int mi = 0; mi < 2; mi++) {
            int ra = wm + mi * 16 + group;
            float s0 = ssbuf[ra] + ssbuf[128 + ra] + ssbuf[256 + ra] + ssbuf[384 + ra];
            int rb = ra + 8;
            float s1 = ssbuf[rb] + ssbuf[128 + rb] + ssbuf[256 + rb] + ssbuf[384 + rb];
            float i0 = rsqrtf(s0), i1 = rsqrtf(s1);
            #pragma unroll
            for (int ni = 0; ni < 8; ni++) {
                acc[mi][ni][0] *= i0; acc[mi][ni][1] *= i0;
                acc[mi][ni][2] *= i1; acc[mi][ni][3] *= i1;
            }
        }
    }

    #pragma unroll
    for (int mi = 0; mi < 2; mi++) {
        size_t rA = r0 + wm + mi * 16 + group;
        #pragma unroll
        for (int ni = 0; ni < 8; ni++) {
            int c = n0 + wn + ni * 8 + t4 * 2;
            *(__nv_bfloat162*)&C[rA * HD + c] =
                __floats2bfloat162_rn(acc[mi][ni][0], acc[mi][ni][1]);
            *(__nv_bfloat162*)&C[(rA + 8) * HD + c] =
                __floats2bfloat162_rn(acc[mi][ni][2], acc[mi][ni][3]);
        }
    }
}

// ---------------- ksum (column sums of kn) -----------------------------------
__global__ void ksum_p_kernel() {
    int c = blockIdx.x * 256 + threadIdx.x;   // grid.x = 4
    int p = blockIdx.y;                        // grid.y = 64
    size_t r0 = (size_t)p * 1024;
    float s = 0.f;
    for (int r = 0; r < 1024; r++) s += __bfloat162float(g_k[(r0 + r) * HD + c]);
    g_ksum_p[p * HD + c] = s;
}
__global__ void ksum_red_kernel() {
    int c = blockIdx.x * 256 + threadIdx.x;   // grid.x = 4
    float s = 0.f;
    for (int p = 0; p < 64; p++) s += g_ksum_p[p * HD + c];
    g_ksum[c] = s;
}

// ---------------- invden[n,h] = 1/(qn . ksum[h] + N)  (read-only q) ----------
__global__ void invden_kernel() {
    int wg = blockIdx.x * 8 + (threadIdx.x >> 5);   // wg = n*4+h
    int lane = threadIdx.x & 31, h = wg & 3;
    size_t base = (size_t)wg * 256 + lane * 8;
    uint4 raw = *(const uint4*)&g_q[base];
    __nv_bfloat162* p = (__nv_bfloat162*)&raw;
    const float* ks = &g_ksum[h * 256 + lane * 8];
    float s = 0.f;
    #pragma unroll
    for (int i = 0; i < 4; i++) {
        float2 f = __bfloat1622float2(p[i]);
        s += f.x * ks[2 * i] + f.y * ks[2 * i + 1];
    }
    #pragma unroll
    for (int o = 16; o > 0; o >>= 1) s += __shfl_xor_sync(0xffffffffu, s, o);
    if (lane == 0) g_invden[wg] = 1.f / (s + 65536.f);
}

// ---------------- kv[h] = kn^T @ v, split-K, 3-stage pipeline ----------------
#define KVA_PITCH 136
#define KVB_PITCH 264
#define KVA_STG (64 * KVA_PITCH)
#define KVB_STG (64 * KVB_PITCH)
#define KV_SMEM_BYTES ((3 * (KVA_STG + KVB_STG)) * 2)

__global__ __launch_bounds__(512) void kv_kernel() {
    extern __shared__ __nv_bfloat16 sm[];
    __nv_bfloat16* As = sm;                   // [3][64][KVA_PITCH]  kn[n][m]
    __nv_bfloat16* Bs = sm + 3 * KVA_STG;     // [3][64][KVB_PITCH]  v[n][d]

    int tid = threadIdx.x, lane = tid & 31, warp = tid >> 5;
    int wm = (warp & 3) * 32, wn = (warp >> 2) * 64;
    int h = blockIdx.z & 3;
    int chunk = blockIdx.z >> 2;
    size_t n0 = (size_t)chunk * 4096;
    int m0 = blockIdx.y * 128;
    int quad = lane >> 3, r8 = lane & 7;
    int arow = tid >> 4, aseg = tid & 15;
    int brow = tid >> 5, bseg = tid & 31;

    float acc[2][8][4];
    #pragma unroll
    for (int a = 0; a < 2; a++)
        #pragma unroll
        for (int b = 0; b < 8; b++)
            #pragma unroll
            for (int c = 0; c < 4; c++) acc[a][b][c] = 0.f;

    auto load_stage = [&](int st, int kk) {
        #pragma unroll
        for (int rr = 0; rr < 2; rr++)
            cp16(&As[st * KVA_STG + (arow + rr * 32) * KVA_PITCH + aseg * 8],
                 &g_k[(n0 + kk + arow + rr * 32) * HD + h * 256 + m0 + aseg * 8]);
        #pragma unroll
        for (int rr = 0; rr < 4; rr++)
            cp16(&Bs[st * KVB_STG + (brow + rr * 16) * KVB_PITCH + bseg * 8],
                 &g_v[(n0 + kk + brow + rr * 16) * HD + h * 256 + bseg * 8]);
        cp_commit();
    };

    load_stage(0, 0);
    load_stage(1, 64);
    #pragma unroll 1
    for (int it = 0; it < 64; it++) {
        int st = it % 3;
        if (it < 63) cp_wait<1>(); else cp_wait<0>();
        __syncthreads();
        if (it + 2 < 64) load_stage((it + 2) % 3, (it + 2) * 64);
        #pragma unroll
        for (int ks = 0; ks < 64; ks += 16) {
            uint32_t af[2][4], bf[4][4];
            #pragma unroll
            for (int mi = 0; mi < 2; mi++)
                ldsm4t(af[mi], smem_u32(&As[st * KVA_STG +
                    (ks + (quad >> 1) * 8 + r8) * KVA_PITCH + wm + mi * 16 + (quad & 1) * 8]));
            #pragma unroll
            for (int nj = 0; nj < 4; nj++)
                ldsm4t(bf[nj], smem_u32(&Bs[st * KVB_STG +
                    (ks + (quad & 1) * 8 + r8) * KVB_PITCH + wn + nj * 16 + (quad >> 1) * 8]));
            #pragma unroll
            for (int mi = 0; mi < 2; mi++)
                #pragma unroll
                for (int nj = 0; nj < 4; nj++) {
                    mma16816(acc[mi][2 * nj],     af[mi], &bf[nj][0]);
                    mma16816(acc[mi][2 * nj + 1], af[mi], &bf[nj][2]);
                }
        }
    }
    int group = lane >> 2, t4 = lane & 3;
    float* dst = &g_kv_part[(size_t)chunk * (4 * DIM * DIM) + h * (DIM * DIM)];
    #pragma unroll
    for (int mi = 0; mi < 2; mi++) {
        int rm = m0 + wm + mi * 16 + group;
        #pragma unroll
        for (int ni = 0; ni < 8; ni++) {
            int c = wn + ni * 8 + t4 * 2;
            *(float2*)&dst[rm * 256 + c]       = make_float2(acc[mi][ni][0], acc[mi][ni][1]);
            *(float2*)&dst[(rm + 8) * 256 + c] = make_float2(acc[mi][ni][2], acc[mi][ni][3]);
        }
    }
}

__global__ void kvred_kernel() {
    int i = blockIdx.x * 256 + threadIdx.x;
    float s = 0.f;
    #pragma unroll
    for (int p = 0; p < 16; p++) s += g_kv_part[p * (4 * DIM * DIM) + i];
    g_kvb[i] = __float2bfloat16(s);
}

// ---------------- out = 0.25*((q*invden) @ kv_stacked + rowoff), K=1024 ------
__global__ __launch_bounds__(512) void out_kernel(float* __restrict__ out) {
    extern __shared__ __nv_bfloat16 sm[];
    __nv_bfloat16* As = sm;                  // [3][128][APITCH]
    __nv_bfloat16* Bs = sm + 3 * ASTG;       // [3][64][BPITCH]

    size_t r0 = (size_t)blockIdx.y * 128;
    int tid = threadIdx.x, lane = tid & 31, warp = tid >> 5;
    int wm = (warp & 3) * 32, wn = (warp >> 2) * 64;
    int quad = lane >> 3, r8 = lane & 7;
    int arow = tid >> 3, aseg = tid & 7;
    int brow = tid >> 5, bseg = tid & 31;

    float acc[2][8][4];
    #pragma unroll
    for (int a = 0; a < 2; a++)
        #pragma unroll
        for (int b = 0; b < 8; b++)
            #pragma unroll
            for (int c = 0; c < 4; c++) acc[a][b][c] = 0.f;

    uint4 aR[2];
    float invR[2];

    auto ldgA = [&](int kit) {       // load q tile for stage kit into regs
        int k0 = kit * 64, h = k0 >> 8;
        #pragma unroll
        for (int rr = 0; rr < 2; rr++) {
            size_t row = r0 + arow + rr * 64;
            aR[rr] = *(const uint4*)&g_q[row * HD + k0 + aseg * 8];
            invR[rr] = g_invden[row * 4 + h];
        }
    };
    auto stsA = [&](int kit) {       // scale by invden, store to smem
        int st = kit % 3;
        #pragma unroll
        for (int rr = 0; rr < 2; rr++) {
            __nv_bfloat162* p = (__nv_bfloat162*)&aR[rr];
            float iv = invR[rr];
            uint4 o;
            __nv_bfloat162* q = (__nv_bfloat162*)&o;
            #pragma unroll
            for (int j = 0; j < 4; j++) {
                float2 f = __bfloat1622float2(p[j]);
                q[j] = __floats2bfloat162_rn(f.x * iv, f.y * iv);
            }
            *(uint4*)&As[st * ASTG + (arow + rr * 64) * APITCH + aseg * 8] = o;
        }
    };
    auto cpB = [&](int kit) {
        int st = kit % 3, k0 = kit * 64;
        #pragma unroll
        for (int rr = 0; rr < 4; rr++)
            cp16(&Bs[st * BSTG + (brow + rr * 16) * BPITCH + bseg * 8],
                 &g_kvb[(size_t)(k0 + brow + rr * 16) * 256 + bseg * 8]);
        cp_commit();
    };

    ldgA(0); stsA(0);
    ldgA(1);                        // held in regs for iter 0
    cpB(0); cpB(1);
    #pragma unroll 1
    for (int it = 0; it < 16; it++) {
        int st = it % 3;
        if (it < 15) cp_wait<1>(); else cp_wait<0>();
        __syncthreads();
        if (it + 1 < 16) stsA(it + 1);
        if (it + 2 < 16) { ldgA(it + 2); cpB(it + 2); }
        #pragma unroll
        for (int ks = 0; ks < 64; ks += 16) {
            uint32_t af[2][4], bf[4][4];
            #pragma unroll
            for (int mi = 0; mi < 2; mi++)
                ldsm4(af[mi], smem_u32(&As[st * ASTG +
                    (wm + mi * 16 + (quad & 1) * 8 + r8) * APITCH + ks + (quad >> 1) * 8]));
            #pragma unroll
            for (int nj = 0; nj < 4; nj++)
                ldsm4t(bf[nj], smem_u32(&Bs[st * BSTG +
                    (ks + (quad & 1) * 8 + r8) * BPITCH + wn + nj * 16 + (quad >> 1) * 8]));
            #pragma unroll
            for (int mi = 0; mi < 2; mi++)
                #pragma unroll
                for (int nj = 0; nj < 4; nj++) {
                    mma16816(acc[mi][2 * nj],     af[mi], &bf[nj][0]);
                    mma16816(acc[mi][2 * nj + 1], af[mi], &bf[nj][2]);
                }
        }
    }

    int group = lane >> 2, t4 = lane & 3;
    #pragma unroll
    for (int mi = 0; mi < 2; mi++) {
        size_t rA = r0 + wm + mi * 16 + group;
        size_t rB = rA + 8;
        float ia[4], ib[4];
        #pragma unroll
        for (int h = 0; h < 4; h++) {
            ia[h] = g_invden[rA * 4 + h];
            ib[h] = g_invden[rB * 4 + h];
        }
        #pragma unroll
        for (int ni = 0; ni < 8; ni++) {
            int c = wn + ni * 8 + t4 * 2;
            float roa0 = 0.f, roa1 = 0.f, rob0 = 0.f, rob1 = 0.f;
            #pragma unroll
            for (int h = 0; h < 4; h++) {
                float v0 = __ldg(&g_vsum[h * 256 + c]);
                float v1 = __ldg(&g_vsum[h * 256 + c + 1]);
                roa0 += ia[h] * v0; roa1 += ia[h] * v1;
                rob0 += ib[h] * v0; rob1 += ib[h] * v1;
            }
            *(float2*)&out[rA * 256 + c] =
                make_float2(0.25f * (acc[mi][ni][0] + roa0), 0.25f * (acc[mi][ni][1] + roa1));
            *(float2*)&out[rB * 256 + c] =
                make_float2(0.25f * (acc[mi][ni][2] + rob0), 0.25f * (acc[mi][ni][3] + rob1));
        }
    }
}

// ---------------- launch -----------------------------------------------------
extern "C" void kernel_launch(void* const* d_in, const int* in_sizes, int n_in,
                              void* d_out, int out_size) {
    const float* x  = (const float*)d_in[0];
    const float* Wq = (const float*)d_in[1];
    const float* bq = (const float*)d_in[2];
    const float* Wk = (const float*)d_in[3];
    const float* bk = (const float*)d_in[4];
    const float* Wv = (const float*)d_in[5];
    const float* bv = (const float*)d_in[6];
    float* out = (float*)d_out;

    cudaFuncSetAttribute(qkv_kernel, cudaFuncAttributeMaxDynamicSharedMemorySize, GEMM_SMEM_BYTES);
    cudaFuncSetAttribute(out_kernel, cudaFuncAttributeMaxDynamicSharedMemorySize, GEMM_SMEM_BYTES);
    cudaFuncSetAttribute(kv_kernel,  cudaFuncAttributeMaxDynamicSharedMemorySize, KV_SMEM_BYTES);

    cvt_x_kernel<<<256, 256>>>(x);                        // 0
    cvt_w_kernel<<<dim3(512, 3), 256>>>(Wq, Wk, Wv);      // 1
    colsum_red_kernel<<<2, 256>>>();                      // 2
    qkv_kernel<<<dim3(12, 512), 512, GEMM_SMEM_BYTES>>>(bq, bk, bv);   // 3 (profiled)
    vsum_kernel<<<128, 256>>>(Wv, bv);                    // 4
    ksum_p_kernel<<<dim3(4, 64), 256>>>();                // 5
    ksum_red_kernel<<<4, 256>>>();                        // 6
    invden_kernel<<<32768, 256>>>();                      // 7
    kv_kernel<<<dim3(1, 2, 64), 512, KV_SMEM_BYTES>>>();  // 8
    kvred_kernel<<<1024, 256>>>();                        // 9
    out_kernel<<<dim3(1, 512), 512, GEMM_SMEM_BYTES>>>(out);  // 10
}